// round 1
// baseline (speedup 1.0000x reference)
#include <cuda_runtime.h>

// Problem constants (fixed by the reference)
#define NMAX 200000
#define EMAX 6400000

// Scratch (device globals — no allocation allowed)
__device__ int   g_deg[NMAX];
__device__ float g_dinv[NMAX];
__device__ float g_tmp[NMAX * 4];   // linear output of current layer (max fout=4)
__device__ float g_agg[NMAX * 4];   // edge aggregation buffer
__device__ float g_h[NMAX * 4];     // hidden activations (layer input/output)

static inline int cdiv(int a, int b) { return (a + b - 1) / b; }

// ---------------- utility zeroing ----------------
__global__ void zero_int_kernel(int* p, int n) {
    int i = blockIdx.x * blockDim.x + threadIdx.x;
    if (i < n) p[i] = 0;
}
__global__ void zero_float_kernel(float* p, int n) {
    int i = blockIdx.x * blockDim.x + threadIdx.x;
    if (i < n) p[i] = 0.0f;
}

// ---------------- degree / normalization ----------------
__global__ void count_deg_kernel(const int* __restrict__ dst, int e) {
    int i = blockIdx.x * blockDim.x + threadIdx.x;
    if (i < e) atomicAdd(&g_deg[dst[i]], 1);
}
__global__ void dinv_kernel(int n) {
    int i = blockIdx.x * blockDim.x + threadIdx.x;
    if (i < n) g_dinv[i] = rsqrtf((float)(g_deg[i] + 1));  // +1 self-loop; always > 0
}

// ---------------- layer-1 GEMM: [n,128] @ [128,4] -> g_tmp ----------------
// One warp per node. Lane l loads x[node, 4l..4l+3] as float4 (coalesced),
// accumulates partial dots for the 4 outputs, warp-reduces.
__global__ void gemm128x4_kernel(const float* __restrict__ x,
                                 const float* __restrict__ W, int n) {
    __shared__ float Ws[128 * 4];
    for (int i = threadIdx.x; i < 512; i += blockDim.x) Ws[i] = W[i];
    __syncthreads();

    int gwarp = (blockIdx.x * blockDim.x + threadIdx.x) >> 5;
    int lane  = threadIdx.x & 31;
    if (gwarp >= n) return;

    float4 xv = *(const float4*)(x + (size_t)gwarp * 128 + lane * 4);
    int k = lane * 4;
    float a0 = xv.x * Ws[(k + 0) * 4 + 0] + xv.y * Ws[(k + 1) * 4 + 0] +
               xv.z * Ws[(k + 2) * 4 + 0] + xv.w * Ws[(k + 3) * 4 + 0];
    float a1 = xv.x * Ws[(k + 0) * 4 + 1] + xv.y * Ws[(k + 1) * 4 + 1] +
               xv.z * Ws[(k + 2) * 4 + 1] + xv.w * Ws[(k + 3) * 4 + 1];
    float a2 = xv.x * Ws[(k + 0) * 4 + 2] + xv.y * Ws[(k + 1) * 4 + 2] +
               xv.z * Ws[(k + 2) * 4 + 2] + xv.w * Ws[(k + 3) * 4 + 2];
    float a3 = xv.x * Ws[(k + 0) * 4 + 3] + xv.y * Ws[(k + 1) * 4 + 3] +
               xv.z * Ws[(k + 2) * 4 + 3] + xv.w * Ws[(k + 3) * 4 + 3];

    #pragma unroll
    for (int off = 16; off > 0; off >>= 1) {
        a0 += __shfl_down_sync(0xffffffffu, a0, off);
        a1 += __shfl_down_sync(0xffffffffu, a1, off);
        a2 += __shfl_down_sync(0xffffffffu, a2, off);
        a3 += __shfl_down_sync(0xffffffffu, a3, off);
    }
    if (lane == 0)
        *(float4*)(g_tmp + (size_t)gwarp * 4) = make_float4(a0, a1, a2, a3);
}

// ---------------- small GEMMs (fin=4 -> fout) : g_h @ W -> g_tmp ----------------
template <int FOUT>
__global__ void gemm4xF_kernel(const float* __restrict__ W, int n) {
    int i = blockIdx.x * blockDim.x + threadIdx.x;
    if (i >= n) return;
    float4 hv = *(const float4*)(g_h + (size_t)i * 4);
    #pragma unroll
    for (int j = 0; j < FOUT; j++) {
        float v = hv.x * __ldg(&W[0 * FOUT + j]) + hv.y * __ldg(&W[1 * FOUT + j]) +
                  hv.z * __ldg(&W[2 * FOUT + j]) + hv.w * __ldg(&W[3 * FOUT + j]);
        g_tmp[(size_t)i * FOUT + j] = v;
    }
}

// ---------------- edge aggregation: agg[dst] += tmp[src] * dinv[s]*dinv[d] ----------------
template <int FOUT>
__global__ void edge_agg_kernel(const int* __restrict__ src,
                                const int* __restrict__ dst, int e) {
    int i = blockIdx.x * blockDim.x + threadIdx.x;
    if (i >= e) return;
    int s = src[i], d = dst[i];
    float w = g_dinv[s] * g_dinv[d];
    if (FOUT == 4) {
        float4 m = *(const float4*)(g_tmp + (size_t)s * 4);
        atomicAdd(&g_agg[(size_t)d * 4 + 0], m.x * w);
        atomicAdd(&g_agg[(size_t)d * 4 + 1], m.y * w);
        atomicAdd(&g_agg[(size_t)d * 4 + 2], m.z * w);
        atomicAdd(&g_agg[(size_t)d * 4 + 3], m.w * w);
    } else {
        float2 m = *(const float2*)(g_tmp + (size_t)s * 2);
        atomicAdd(&g_agg[(size_t)d * 2 + 0], m.x * w);
        atomicAdd(&g_agg[(size_t)d * 2 + 1], m.y * w);
    }
}

// ---------------- finalize: h = tanh(agg + tmp*dinv^2 + b) ----------------
template <int FOUT>
__global__ void finalize_kernel(const float* __restrict__ b, int n) {
    int i = blockIdx.x * blockDim.x + threadIdx.x;
    if (i >= n) return;
    float di = g_dinv[i];
    float wl = di * di;  // self-loop weight
    #pragma unroll
    for (int j = 0; j < FOUT; j++) {
        float v = g_agg[(size_t)i * FOUT + j] +
                  g_tmp[(size_t)i * FOUT + j] * wl + __ldg(&b[j]);
        g_h[(size_t)i * FOUT + j] = tanhf(v);
    }
}

// ---------------- classifier + output write ----------------
// out[:, :16] = h3 @ Wc + bc ; also copy h3 into the second output region.
__global__ void classifier_kernel(const float* __restrict__ Wc,
                                  const float* __restrict__ bc,
                                  float* __restrict__ out,
                                  float* __restrict__ hsec, int n) {
    int idx = blockIdx.x * blockDim.x + threadIdx.x;
    int node = idx >> 4;
    int c = idx & 15;
    if (node >= n) return;
    float h0 = g_h[(size_t)node * 2 + 0];
    float h1 = g_h[(size_t)node * 2 + 1];
    float v = h0 * __ldg(&Wc[0 * 16 + c]) + h1 * __ldg(&Wc[1 * 16 + c]) + __ldg(&bc[c]);
    out[(size_t)node * 16 + c] = v;
    if (c < 2) hsec[(size_t)node * 2 + c] = (c == 0) ? h0 : h1;
}

extern "C" void kernel_launch(void* const* d_in, const int* in_sizes, int n_in,
                              void* d_out, int out_size) {
    const float* x  = (const float*)d_in[0];
    const float* W1 = (const float*)d_in[1];
    const float* b1 = (const float*)d_in[2];
    const float* W2 = (const float*)d_in[3];
    const float* b2 = (const float*)d_in[4];
    const float* W3 = (const float*)d_in[5];
    const float* b3 = (const float*)d_in[6];
    const float* Wc = (const float*)d_in[7];
    const float* bc = (const float*)d_in[8];
    const int*   ei = (const int*)d_in[9];

    const int n = in_sizes[0] / 128;   // N
    const int e = in_sizes[9] / 2;     // E
    const int* src = ei;
    const int* dst = ei + e;

    const int B = 256;

    // device-symbol addresses (lookup only; no allocation)
    int*   deg_p;  cudaGetSymbolAddress((void**)&deg_p,  g_deg);
    float* agg_p;  cudaGetSymbolAddress((void**)&agg_p,  g_agg);

    // --- degree + normalization ---
    zero_int_kernel<<<cdiv(n, B), B>>>(deg_p, n);
    count_deg_kernel<<<cdiv(e, B), B>>>(dst, e);
    dinv_kernel<<<cdiv(n, B), B>>>(n);

    // --- layer 1: 128 -> 4 ---
    gemm128x4_kernel<<<cdiv(n * 32, B), B>>>(x, W1, n);
    zero_float_kernel<<<cdiv(n * 4, B), B>>>(agg_p, n * 4);
    edge_agg_kernel<4><<<cdiv(e, B), B>>>(src, dst, e);
    finalize_kernel<4><<<cdiv(n, B), B>>>(b1, n);

    // --- layer 2: 4 -> 4 ---
    gemm4xF_kernel<4><<<cdiv(n, B), B>>>(W2, n);
    zero_float_kernel<<<cdiv(n * 4, B), B>>>(agg_p, n * 4);
    edge_agg_kernel<4><<<cdiv(e, B), B>>>(src, dst, e);
    finalize_kernel<4><<<cdiv(n, B), B>>>(b2, n);

    // --- layer 3: 4 -> 2 ---
    gemm4xF_kernel<2><<<cdiv(n, B), B>>>(W3, n);
    zero_float_kernel<<<cdiv(n * 2, B), B>>>(agg_p, n * 2);
    edge_agg_kernel<2><<<cdiv(e, B), B>>>(src, dst, e);
    finalize_kernel<2><<<cdiv(n, B), B>>>(b3, n);

    // --- classifier + outputs ---
    float* out  = (float*)d_out;
    float* hsec = out + (size_t)n * 16;
    classifier_kernel<<<cdiv(n * 16, B), B>>>(Wc, bc, out, hsec, n);
}

// round 3
// speedup vs baseline: 1.9210x; 1.9210x over previous
#include <cuda_runtime.h>
#include <cstdint>

#define NMAX 200000
#define EMAX 6400000

// Scratch (device globals — no allocation allowed)
__device__ int   g_deg[NMAX];
__device__ __align__(16) float g_dinv[NMAX];
__device__ __align__(16) float g_w[EMAX];        // per-edge norm weight (computed in pass 1)
__device__ __align__(16) float g_tmpA[NMAX * 4];
__device__ __align__(16) float g_tmpB[NMAX * 4];
__device__ __align__(16) float g_agg[NMAX * 4];

static inline int cdiv(int a, int b) { return (a + b - 1) / b; }

// ---------------- init: zero deg + agg ----------------
__global__ void init_kernel(int n) {
    int i = blockIdx.x * blockDim.x + threadIdx.x;
    if (i >= n) return;
    g_deg[i] = 0;
    ((float4*)g_agg)[i] = make_float4(0.f, 0.f, 0.f, 0.f);
}

// ---------------- degree count (4 edges/thread) ----------------
__global__ void count_deg_kernel(const int* __restrict__ dst, int e) {
    int t = blockIdx.x * blockDim.x + threadIdx.x;
    int base = t * 4;
    if (base >= e) return;
    if (base + 4 <= e) {
        int4 d4 = *(const int4*)(dst + base);
        atomicAdd(&g_deg[d4.x], 1);
        atomicAdd(&g_deg[d4.y], 1);
        atomicAdd(&g_deg[d4.z], 1);
        atomicAdd(&g_deg[d4.w], 1);
    } else {
        for (int i = base; i < e; i++) atomicAdd(&g_deg[dst[i]], 1);
    }
}

__global__ void dinv_kernel(int n) {
    int i = blockIdx.x * blockDim.x + threadIdx.x;
    if (i < n) g_dinv[i] = rsqrtf((float)(g_deg[i] + 1));  // +1 self-loop
}

// ---------------- layer-1 GEMM: [n,128] @ [128,4] -> g_tmpA ----------------
// Warp per node (grid-stride). Weights live in registers (loaded once per warp),
// so per-node L1 traffic is just the coalesced float4 x-load.
__global__ void gemm128x4_kernel(const float* __restrict__ x,
                                 const float* __restrict__ W, int n) {
    int lane = threadIdx.x & 31;
    // lane handles k = 4*lane .. 4*lane+3 ; row k of W is W[k*4 .. k*4+3]
    float4 w0 = *(const float4*)(W + (lane * 4 + 0) * 4);
    float4 w1 = *(const float4*)(W + (lane * 4 + 1) * 4);
    float4 w2 = *(const float4*)(W + (lane * 4 + 2) * 4);
    float4 w3 = *(const float4*)(W + (lane * 4 + 3) * 4);

    int warp_id = (blockIdx.x * blockDim.x + threadIdx.x) >> 5;
    int nwarps  = (gridDim.x * blockDim.x) >> 5;

    for (int node = warp_id; node < n; node += nwarps) {
        float4 xv = *(const float4*)(x + (size_t)node * 128 + lane * 4);
        float a0 = xv.x * w0.x + xv.y * w1.x + xv.z * w2.x + xv.w * w3.x;
        float a1 = xv.x * w0.y + xv.y * w1.y + xv.z * w2.y + xv.w * w3.y;
        float a2 = xv.x * w0.z + xv.y * w1.z + xv.z * w2.z + xv.w * w3.z;
        float a3 = xv.x * w0.w + xv.y * w1.w + xv.z * w2.w + xv.w * w3.w;
        #pragma unroll
        for (int off = 16; off > 0; off >>= 1) {
            a0 += __shfl_down_sync(0xffffffffu, a0, off);
            a1 += __shfl_down_sync(0xffffffffu, a1, off);
            a2 += __shfl_down_sync(0xffffffffu, a2, off);
            a3 += __shfl_down_sync(0xffffffffu, a3, off);
        }
        if (lane == 0)
            *(float4*)(g_tmpA + (size_t)node * 4) = make_float4(a0, a1, a2, a3);
    }
}

// ---------------- edge aggregation ----------------
template <int FOUT>
__device__ __forceinline__ void do_edge(int s, int d, float w,
                                        const float* __restrict__ tmp) {
    if (FOUT == 4) {
        float4 m = *(const float4*)(tmp + (size_t)s * 4);
        m.x *= w; m.y *= w; m.z *= w; m.w *= w;
        atomicAdd((float4*)(g_agg + (size_t)d * 4), m);
    } else {
        float2 m = *(const float2*)(tmp + (size_t)s * 2);
        m.x *= w; m.y *= w;
        atomicAdd((float2*)(g_agg + (size_t)d * 2), m);
    }
}

template <int FOUT, bool FIRST>
__global__ void edge_pass_kernel(const int* __restrict__ src,
                                 const int* __restrict__ dst,
                                 const float* __restrict__ tmp, int e) {
    int t = blockIdx.x * blockDim.x + threadIdx.x;
    int base = t * 4;
    if (base >= e) return;
    if (base + 4 <= e) {
        int4 s4 = *(const int4*)(src + base);
        int4 d4 = *(const int4*)(dst + base);
        float4 wv;
        if (FIRST) {
            wv.x = g_dinv[s4.x] * g_dinv[d4.x];
            wv.y = g_dinv[s4.y] * g_dinv[d4.y];
            wv.z = g_dinv[s4.z] * g_dinv[d4.z];
            wv.w = g_dinv[s4.w] * g_dinv[d4.w];
            *(float4*)(g_w + base) = wv;
        } else {
            wv = *(const float4*)(g_w + base);
        }
        do_edge<FOUT>(s4.x, d4.x, wv.x, tmp);
        do_edge<FOUT>(s4.y, d4.y, wv.y, tmp);
        do_edge<FOUT>(s4.z, d4.z, wv.z, tmp);
        do_edge<FOUT>(s4.w, d4.w, wv.w, tmp);
    } else {
        for (int i = base; i < e; i++) {
            int s = src[i], d = dst[i];
            float w;
            if (FIRST) { w = g_dinv[s] * g_dinv[d]; g_w[i] = w; }
            else       { w = g_w[i]; }
            do_edge<FOUT>(s, d, w, tmp);
        }
    }
}

// scalar fallback (only if e % 4 != 0 or dst misaligned)
template <int FOUT, bool FIRST>
__global__ void edge_pass_scalar_kernel(const int* __restrict__ src,
                                        const int* __restrict__ dst,
                                        const float* __restrict__ tmp, int e) {
    int i = blockIdx.x * blockDim.x + threadIdx.x;
    if (i >= e) return;
    int s = src[i], d = dst[i];
    float w;
    if (FIRST) { w = g_dinv[s] * g_dinv[d]; g_w[i] = w; }
    else       { w = g_w[i]; }
    do_edge<FOUT>(s, d, w, tmp);
}

// ---------------- finalize layer (FOUT=4) fused with next GEMM (4 -> FNEXT) ----------------
// h = tanh(agg + tmp*dinv^2 + b) ; tmp_next = h @ Wn ; agg reset for next pass.
template <int FNEXT>
__global__ void finalize_gemm_kernel(const float* __restrict__ tmp,
                                     const float* __restrict__ b,
                                     const float* __restrict__ Wn,
                                     float* __restrict__ tmp_next, int n) {
    int i = blockIdx.x * blockDim.x + threadIdx.x;
    if (i >= n) return;
    float di = g_dinv[i];
    float wl = di * di;
    float4 a  = *(const float4*)(g_agg + (size_t)i * 4);
    float4 tv = *(const float4*)(tmp + (size_t)i * 4);
    float h0 = tanhf(a.x + tv.x * wl + __ldg(&b[0]));
    float h1 = tanhf(a.y + tv.y * wl + __ldg(&b[1]));
    float h2 = tanhf(a.z + tv.z * wl + __ldg(&b[2]));
    float h3 = tanhf(a.w + tv.w * wl + __ldg(&b[3]));
    *(float4*)(g_agg + (size_t)i * 4) = make_float4(0.f, 0.f, 0.f, 0.f);

    if (FNEXT == 4) {
        float4 o;
        o.x = h0 * __ldg(&Wn[0*4+0]) + h1 * __ldg(&Wn[1*4+0]) + h2 * __ldg(&Wn[2*4+0]) + h3 * __ldg(&Wn[3*4+0]);
        o.y = h0 * __ldg(&Wn[0*4+1]) + h1 * __ldg(&Wn[1*4+1]) + h2 * __ldg(&Wn[2*4+1]) + h3 * __ldg(&Wn[3*4+1]);
        o.z = h0 * __ldg(&Wn[0*4+2]) + h1 * __ldg(&Wn[1*4+2]) + h2 * __ldg(&Wn[2*4+2]) + h3 * __ldg(&Wn[3*4+2]);
        o.w = h0 * __ldg(&Wn[0*4+3]) + h1 * __ldg(&Wn[1*4+3]) + h2 * __ldg(&Wn[2*4+3]) + h3 * __ldg(&Wn[3*4+3]);
        *(float4*)(tmp_next + (size_t)i * 4) = o;
    } else {
        float2 o;
        o.x = h0 * __ldg(&Wn[0*2+0]) + h1 * __ldg(&Wn[1*2+0]) + h2 * __ldg(&Wn[2*2+0]) + h3 * __ldg(&Wn[3*2+0]);
        o.y = h0 * __ldg(&Wn[0*2+1]) + h1 * __ldg(&Wn[1*2+1]) + h2 * __ldg(&Wn[2*2+1]) + h3 * __ldg(&Wn[3*2+1]);
        *(float2*)(tmp_next + (size_t)i * 2) = o;
    }
}

// ---------------- finalize layer 3 (FOUT=2) fused with classifier + output write ----------------
__global__ void finalize_cls_kernel(const float* __restrict__ tmp,
                                    const float* __restrict__ b3,
                                    const float* __restrict__ Wc,
                                    const float* __restrict__ bc,
                                    float* __restrict__ out,
                                    float* __restrict__ hsec, int n) {
    int i = blockIdx.x * blockDim.x + threadIdx.x;
    if (i >= n) return;
    float di = g_dinv[i];
    float wl = di * di;
    float2 a  = *(const float2*)(g_agg + (size_t)i * 2);
    float2 tv = *(const float2*)(tmp + (size_t)i * 2);
    float h0 = tanhf(a.x + tv.x * wl + __ldg(&b3[0]));
    float h1 = tanhf(a.y + tv.y * wl + __ldg(&b3[1]));
    *(float2*)(hsec + (size_t)i * 2) = make_float2(h0, h1);
    #pragma unroll
    for (int j0 = 0; j0 < 16; j0 += 4) {
        float4 v;
        v.x = h0 * __ldg(&Wc[0*16 + j0+0]) + h1 * __ldg(&Wc[1*16 + j0+0]) + __ldg(&bc[j0+0]);
        v.y = h0 * __ldg(&Wc[0*16 + j0+1]) + h1 * __ldg(&Wc[1*16 + j0+1]) + __ldg(&bc[j0+1]);
        v.z = h0 * __ldg(&Wc[0*16 + j0+2]) + h1 * __ldg(&Wc[1*16 + j0+2]) + __ldg(&bc[j0+2]);
        v.w = h0 * __ldg(&Wc[0*16 + j0+3]) + h1 * __ldg(&Wc[1*16 + j0+3]) + __ldg(&bc[j0+3]);
        *(float4*)(out + (size_t)i * 16 + j0) = v;
    }
}

extern "C" void kernel_launch(void* const* d_in, const int* in_sizes, int n_in,
                              void* d_out, int out_size) {
    const float* x  = (const float*)d_in[0];
    const float* W1 = (const float*)d_in[1];
    const float* b1 = (const float*)d_in[2];
    const float* W2 = (const float*)d_in[3];
    const float* b2 = (const float*)d_in[4];
    const float* W3 = (const float*)d_in[5];
    const float* b3 = (const float*)d_in[6];
    const float* Wc = (const float*)d_in[7];
    const float* bc = (const float*)d_in[8];
    const int*   ei = (const int*)d_in[9];

    const int n = in_sizes[0] / 128;
    const int e = in_sizes[9] / 2;
    const int* src = ei;
    const int* dst = ei + e;

    const int B = 256;
    const bool vec = ((e & 3) == 0) &&
                     ((((unsigned long long)(uintptr_t)dst) & 15ull) == 0) &&
                     ((((unsigned long long)(uintptr_t)src) & 15ull) == 0);

    float* tmpA; cudaGetSymbolAddress((void**)&tmpA, g_tmpA);
    float* tmpB; cudaGetSymbolAddress((void**)&tmpB, g_tmpB);

    // degree + normalization (+ zero agg)
    init_kernel<<<cdiv(n, B), B>>>(n);
    count_deg_kernel<<<cdiv(cdiv(e, 4), B), B>>>(dst, e);
    dinv_kernel<<<cdiv(n, B), B>>>(n);

    // layer 1: 128 -> 4
    gemm128x4_kernel<<<1184, B>>>(x, W1, n);
    if (vec) edge_pass_kernel<4, true><<<cdiv(cdiv(e, 4), B), B>>>(src, dst, tmpA, e);
    else     edge_pass_scalar_kernel<4, true><<<cdiv(e, B), B>>>(src, dst, tmpA, e);
    finalize_gemm_kernel<4><<<cdiv(n, B), B>>>(tmpA, b1, W2, tmpB, n);

    // layer 2: 4 -> 4
    if (vec) edge_pass_kernel<4, false><<<cdiv(cdiv(e, 4), B), B>>>(src, dst, tmpB, e);
    else     edge_pass_scalar_kernel<4, false><<<cdiv(e, B), B>>>(src, dst, tmpB, e);
    finalize_gemm_kernel<2><<<cdiv(n, B), B>>>(tmpB, b2, W3, tmpA, n);

    // layer 3: 4 -> 2
    if (vec) edge_pass_kernel<2, false><<<cdiv(cdiv(e, 4), B), B>>>(src, dst, tmpA, e);
    else     edge_pass_scalar_kernel<2, false><<<cdiv(e, B), B>>>(src, dst, tmpA, e);

    float* out  = (float*)d_out;
    float* hsec = out + (size_t)n * 16;
    finalize_cls_kernel<<<cdiv(n, B), B>>>(tmpA, b3, Wc, bc, out, hsec, n);
}

// round 4
// speedup vs baseline: 1.9636x; 1.0222x over previous
#include <cuda_runtime.h>
#include <cstdint>

#define NMAX 200000
#define EMAX 6400000
#define CHUNK 8192
#define NCHUNKS ((NMAX + CHUNK - 1) / CHUNK)   // 25
#define SIDX_CAP 11776                          // 46KB smem staging for CSR slices

// Scratch (device globals — no allocation allowed)
__device__ int g_deg[NMAX];
__device__ int g_rowoff[NMAX];
__device__ int g_cursor[NMAX];
__device__ int g_csum[NCHUNKS];
__device__ int g_csr[EMAX];
__device__ __align__(16) float g_dinv[NMAX];
__device__ __align__(16) float g_tmpA[NMAX * 4];
__device__ __align__(16) float g_tmpB[NMAX * 4];

static inline int cdiv(int a, int b) { return (a + b - 1) / b; }

// ---------------- zero degree ----------------
__global__ void zero_deg_kernel(int n) {
    int i = blockIdx.x * blockDim.x + threadIdx.x;
    if (i < n) g_deg[i] = 0;
}

// ---------------- degree count ----------------
__global__ void count_deg_kernel(const int* __restrict__ dst, int e) {
    int t = blockIdx.x * blockDim.x + threadIdx.x;
    int base = t * 4;
    if (base >= e) return;
    if (base + 4 <= e) {
        int4 d4 = *(const int4*)(dst + base);
        atomicAdd(&g_deg[d4.x], 1);
        atomicAdd(&g_deg[d4.y], 1);
        atomicAdd(&g_deg[d4.z], 1);
        atomicAdd(&g_deg[d4.w], 1);
    } else {
        for (int i = base; i < e; i++) atomicAdd(&g_deg[dst[i]], 1);
    }
}
__global__ void count_deg_scalar_kernel(const int* __restrict__ dst, int e) {
    int i = blockIdx.x * blockDim.x + threadIdx.x;
    if (i < e) atomicAdd(&g_deg[dst[i]], 1);
}

// ---------------- prefix scan: A (per-chunk), B (chunk totals), C (apply + dinv + cursor) ----------------
__global__ void scanA_kernel(int n) {
    int t = threadIdx.x;                       // 256 threads, 32 nodes each
    int base = blockIdx.x * CHUNK + t * 32;
    int s = 0;
    for (int r = 0; r < 32; r++) {
        int node = base + r;
        if (node < n) s += g_deg[node];
    }
    int lane = t & 31, wid = t >> 5;
    int incl = s;
    #pragma unroll
    for (int off = 1; off < 32; off <<= 1) {
        int v = __shfl_up_sync(0xffffffffu, incl, off);
        if (lane >= off) incl += v;
    }
    __shared__ int wsum[8], woff[8];
    if (lane == 31) wsum[wid] = incl;
    __syncthreads();
    if (t < 8) {
        int acc = 0;
        for (int w = 0; w < t; w++) acc += wsum[w];
        woff[t] = acc;
    }
    __syncthreads();
    int run = incl - s + woff[wid];            // exclusive prefix for this thread
    for (int r = 0; r < 32; r++) {
        int node = base + r;
        if (node < n) { g_rowoff[node] = run; run += g_deg[node]; }
    }
    if (t == 255) g_csum[blockIdx.x] = incl + woff[wid];   // chunk total
}

__global__ void scanB_kernel(int nb) {         // nb <= 32, launch 32 threads
    int t = threadIdx.x;
    int v = (t < nb) ? g_csum[t] : 0;
    int incl = v;
    #pragma unroll
    for (int off = 1; off < 32; off <<= 1) {
        int u = __shfl_up_sync(0xffffffffu, incl, off);
        if (t >= off) incl += u;
    }
    if (t < nb) g_csum[t] = incl - v;          // exclusive
}

__global__ void scanC_kernel(int n) {
    int i = blockIdx.x * blockDim.x + threadIdx.x;
    if (i >= n) return;
    int off = g_rowoff[i] + g_csum[i / CHUNK];
    g_rowoff[i] = off;
    g_cursor[i] = off;
    g_dinv[i] = rsqrtf((float)(g_deg[i] + 1)); // +1 self-loop
}

// ---------------- CSR scatter ----------------
__global__ void scatter_kernel(const int* __restrict__ src, const int* __restrict__ dst, int e) {
    int t = blockIdx.x * blockDim.x + threadIdx.x;
    int base = t * 4;
    if (base >= e) return;
    if (base + 4 <= e) {
        int4 s4 = *(const int4*)(src + base);
        int4 d4 = *(const int4*)(dst + base);
        int p;
        p = atomicAdd(&g_cursor[d4.x], 1); g_csr[p] = s4.x;
        p = atomicAdd(&g_cursor[d4.y], 1); g_csr[p] = s4.y;
        p = atomicAdd(&g_cursor[d4.z], 1); g_csr[p] = s4.z;
        p = atomicAdd(&g_cursor[d4.w], 1); g_csr[p] = s4.w;
    } else {
        for (int i = base; i < e; i++) {
            int p = atomicAdd(&g_cursor[dst[i]], 1);
            g_csr[p] = src[i];
        }
    }
}
__global__ void scatter_scalar_kernel(const int* __restrict__ src, const int* __restrict__ dst, int e) {
    int i = blockIdx.x * blockDim.x + threadIdx.x;
    if (i >= e) return;
    int p = atomicAdd(&g_cursor[dst[i]], 1);
    g_csr[p] = src[i];
}

// ---------------- layer-1 GEMM (smem tile, no shuffles): tmpA = (x @ W1) * dinv ----------------
#define GN 64
__global__ void gemm1_kernel(const float* __restrict__ x, const float* __restrict__ W, int n) {
    __shared__ float4 Wv[128];        // W row k as float4
    __shared__ float4 xs[GN * 33];    // 64 nodes x 32 f4, padded row 33
    __shared__ float4 ps[GN];         // partials from half 1
    int t = threadIdx.x;              // 128 threads
    if (t < 128) Wv[t] = ((const float4*)W)[t];
    int node0 = blockIdx.x * GN;
    int nn = min(GN, n - node0);
    int tot = nn * 32;
    const float4* x4 = (const float4*)x;
    for (int idx = t; idx < tot; idx += 128) {
        int nd = idx >> 5, kq = idx & 31;
        xs[nd * 33 + kq] = x4[(size_t)(node0 + nd) * 32 + kq];
    }
    __syncthreads();
    int half = t >> 6;
    int node = t & 63;
    float4 acc = make_float4(0.f, 0.f, 0.f, 0.f);
    if (node < nn) {
        int k0 = half * 16;
        #pragma unroll
        for (int kq = 0; kq < 16; kq++) {
            float4 xv = xs[node * 33 + k0 + kq];
            float4 w0 = Wv[(k0 + kq) * 4 + 0];
            float4 w1 = Wv[(k0 + kq) * 4 + 1];
            float4 w2 = Wv[(k0 + kq) * 4 + 2];
            float4 w3 = Wv[(k0 + kq) * 4 + 3];
            acc.x += xv.x * w0.x + xv.y * w1.x + xv.z * w2.x + xv.w * w3.x;
            acc.y += xv.x * w0.y + xv.y * w1.y + xv.z * w2.y + xv.w * w3.y;
            acc.z += xv.x * w0.z + xv.y * w1.z + xv.z * w2.z + xv.w * w3.z;
            acc.w += xv.x * w0.w + xv.y * w1.w + xv.z * w2.w + xv.w * w3.w;
        }
    }
    if (half == 1) ps[node] = acc;
    __syncthreads();
    if (half == 0 && node < nn) {
        float4 b = ps[node];
        int i = node0 + node;
        float dv = g_dinv[i];
        float4 o = make_float4((acc.x + b.x) * dv, (acc.y + b.y) * dv,
                               (acc.z + b.z) * dv, (acc.w + b.w) * dv);
        *(float4*)(g_tmpA + (size_t)i * 4) = o;
    }
}

// ---------------- fused pull (FIN=4): aggregate + tanh + next GEMM + prescale ----------------
// tin: prescaled f4 per node; h = tanh(dinv*(sum_in + self) + b); tout = (h@Wn)*dinv
template <int FNEXT>
__global__ void pull4_kernel(const float* __restrict__ tin,
                             const float* __restrict__ b,
                             const float* __restrict__ Wn,
                             float* __restrict__ tout, int n) {
    __shared__ int sidx[SIDX_CAP];
    int node0 = blockIdx.x * 256;
    int t = threadIdx.x;
    int nn = min(256, n - node0);
    int lastn = node0 + nn - 1;
    int base = g_rowoff[node0];
    int cnt = g_rowoff[lastn] + g_deg[lastn] - base;
    bool insm = (cnt <= SIDX_CAP);
    if (insm)
        for (int j = t; j < cnt; j += 256) sidx[j] = g_csr[base + j];
    __syncthreads();

    int i = node0 + t;
    if (i >= n) return;
    const float4* tp = (const float4*)tin;
    float4 a0 = tp[i];  // self-loop term tmp'[i]
    float4 a1 = make_float4(0.f, 0.f, 0.f, 0.f), a2 = a1, a3 = a1;
    int cntl = g_deg[i];
    if (insm) {
        int j = g_rowoff[i] - base, jend = j + cntl;
        for (; j + 4 <= jend; j += 4) {
            float4 v0 = tp[sidx[j]], v1 = tp[sidx[j + 1]], v2 = tp[sidx[j + 2]], v3 = tp[sidx[j + 3]];
            a0.x += v0.x; a0.y += v0.y; a0.z += v0.z; a0.w += v0.w;
            a1.x += v1.x; a1.y += v1.y; a1.z += v1.z; a1.w += v1.w;
            a2.x += v2.x; a2.y += v2.y; a2.z += v2.z; a2.w += v2.w;
            a3.x += v3.x; a3.y += v3.y; a3.z += v3.z; a3.w += v3.w;
        }
        for (; j < jend; j++) {
            float4 v = tp[sidx[j]];
            a0.x += v.x; a0.y += v.y; a0.z += v.z; a0.w += v.w;
        }
    } else {
        int j = g_rowoff[i], jend = j + cntl;
        for (; j + 4 <= jend; j += 4) {
            float4 v0 = tp[g_csr[j]], v1 = tp[g_csr[j + 1]], v2 = tp[g_csr[j + 2]], v3 = tp[g_csr[j + 3]];
            a0.x += v0.x; a0.y += v0.y; a0.z += v0.z; a0.w += v0.w;
            a1.x += v1.x; a1.y += v1.y; a1.z += v1.z; a1.w += v1.w;
            a2.x += v2.x; a2.y += v2.y; a2.z += v2.z; a2.w += v2.w;
            a3.x += v3.x; a3.y += v3.y; a3.z += v3.z; a3.w += v3.w;
        }
        for (; j < jend; j++) {
            float4 v = tp[g_csr[j]];
            a0.x += v.x; a0.y += v.y; a0.z += v.z; a0.w += v.w;
        }
    }
    float dv = g_dinv[i];
    float sx = (a0.x + a1.x) + (a2.x + a3.x);
    float sy = (a0.y + a1.y) + (a2.y + a3.y);
    float sz = (a0.z + a1.z) + (a2.z + a3.z);
    float sw = (a0.w + a1.w) + (a2.w + a3.w);
    float h0 = tanhf(sx * dv + __ldg(&b[0]));
    float h1 = tanhf(sy * dv + __ldg(&b[1]));
    float h2 = tanhf(sz * dv + __ldg(&b[2]));
    float h3 = tanhf(sw * dv + __ldg(&b[3]));
    if (FNEXT == 4) {
        float4 o;
        o.x = (h0*__ldg(&Wn[0*4+0]) + h1*__ldg(&Wn[1*4+0]) + h2*__ldg(&Wn[2*4+0]) + h3*__ldg(&Wn[3*4+0])) * dv;
        o.y = (h0*__ldg(&Wn[0*4+1]) + h1*__ldg(&Wn[1*4+1]) + h2*__ldg(&Wn[2*4+1]) + h3*__ldg(&Wn[3*4+1])) * dv;
        o.z = (h0*__ldg(&Wn[0*4+2]) + h1*__ldg(&Wn[1*4+2]) + h2*__ldg(&Wn[2*4+2]) + h3*__ldg(&Wn[3*4+2])) * dv;
        o.w = (h0*__ldg(&Wn[0*4+3]) + h1*__ldg(&Wn[1*4+3]) + h2*__ldg(&Wn[2*4+3]) + h3*__ldg(&Wn[3*4+3])) * dv;
        *(float4*)(tout + (size_t)i * 4) = o;
    } else {
        float2 o;
        o.x = (h0*__ldg(&Wn[0*2+0]) + h1*__ldg(&Wn[1*2+0]) + h2*__ldg(&Wn[2*2+0]) + h3*__ldg(&Wn[3*2+0])) * dv;
        o.y = (h0*__ldg(&Wn[0*2+1]) + h1*__ldg(&Wn[1*2+1]) + h2*__ldg(&Wn[2*2+1]) + h3*__ldg(&Wn[3*2+1])) * dv;
        *(float2*)(tout + (size_t)i * 2) = o;
    }
}

// ---------------- fused pull (FIN=2) + classifier + outputs ----------------
__global__ void pull2_cls_kernel(const float* __restrict__ tin,
                                 const float* __restrict__ b3,
                                 const float* __restrict__ Wc,
                                 const float* __restrict__ bc,
                                 float* __restrict__ out,
                                 float* __restrict__ hsec, int n) {
    __shared__ int sidx[SIDX_CAP];
    int node0 = blockIdx.x * 256;
    int t = threadIdx.x;
    int nn = min(256, n - node0);
    int lastn = node0 + nn - 1;
    int base = g_rowoff[node0];
    int cnt = g_rowoff[lastn] + g_deg[lastn] - base;
    bool insm = (cnt <= SIDX_CAP);
    if (insm)
        for (int j = t; j < cnt; j += 256) sidx[j] = g_csr[base + j];
    __syncthreads();

    int i = node0 + t;
    if (i >= n) return;
    const float2* tp = (const float2*)tin;
    float2 a0 = tp[i];
    float2 a1 = make_float2(0.f, 0.f), a2 = a1, a3 = a1;
    int cntl = g_deg[i];
    if (insm) {
        int j = g_rowoff[i] - base, jend = j + cntl;
        for (; j + 4 <= jend; j += 4) {
            float2 v0 = tp[sidx[j]], v1 = tp[sidx[j + 1]], v2 = tp[sidx[j + 2]], v3 = tp[sidx[j + 3]];
            a0.x += v0.x; a0.y += v0.y;
            a1.x += v1.x; a1.y += v1.y;
            a2.x += v2.x; a2.y += v2.y;
            a3.x += v3.x; a3.y += v3.y;
        }
        for (; j < jend; j++) { float2 v = tp[sidx[j]]; a0.x += v.x; a0.y += v.y; }
    } else {
        int j = g_rowoff[i], jend = j + cntl;
        for (; j < jend; j++) { float2 v = tp[g_csr[j]]; a0.x += v.x; a0.y += v.y; }
    }
    float dv = g_dinv[i];
    float sx = (a0.x + a1.x) + (a2.x + a3.x);
    float sy = (a0.y + a1.y) + (a2.y + a3.y);
    float h0 = tanhf(sx * dv + __ldg(&b3[0]));
    float h1 = tanhf(sy * dv + __ldg(&b3[1]));
    *(float2*)(hsec + (size_t)i * 2) = make_float2(h0, h1);
    #pragma unroll
    for (int j0 = 0; j0 < 16; j0 += 4) {
        float4 v;
        v.x = h0*__ldg(&Wc[0*16+j0+0]) + h1*__ldg(&Wc[1*16+j0+0]) + __ldg(&bc[j0+0]);
        v.y = h0*__ldg(&Wc[0*16+j0+1]) + h1*__ldg(&Wc[1*16+j0+1]) + __ldg(&bc[j0+1]);
        v.z = h0*__ldg(&Wc[0*16+j0+2]) + h1*__ldg(&Wc[1*16+j0+2]) + __ldg(&bc[j0+2]);
        v.w = h0*__ldg(&Wc[0*16+j0+3]) + h1*__ldg(&Wc[1*16+j0+3]) + __ldg(&bc[j0+3]);
        *(float4*)(out + (size_t)i * 16 + j0) = v;
    }
}

extern "C" void kernel_launch(void* const* d_in, const int* in_sizes, int n_in,
                              void* d_out, int out_size) {
    const float* x  = (const float*)d_in[0];
    const float* W1 = (const float*)d_in[1];
    const float* b1 = (const float*)d_in[2];
    const float* W2 = (const float*)d_in[3];
    const float* b2 = (const float*)d_in[4];
    const float* W3 = (const float*)d_in[5];
    const float* b3 = (const float*)d_in[6];
    const float* Wc = (const float*)d_in[7];
    const float* bc = (const float*)d_in[8];
    const int*   ei = (const int*)d_in[9];

    const int n = in_sizes[0] / 128;
    const int e = in_sizes[9] / 2;
    const int* src = ei;
    const int* dst = ei + e;

    const int B = 256;
    const bool vec = ((e & 3) == 0) &&
                     ((((unsigned long long)(uintptr_t)dst) & 15ull) == 0) &&
                     ((((unsigned long long)(uintptr_t)src) & 15ull) == 0);

    float* tmpA; cudaGetSymbolAddress((void**)&tmpA, g_tmpA);
    float* tmpB; cudaGetSymbolAddress((void**)&tmpB, g_tmpB);

    // build normalization + CSR
    zero_deg_kernel<<<cdiv(n, B), B>>>(n);
    if (vec) count_deg_kernel<<<cdiv(cdiv(e, 4), B), B>>>(dst, e);
    else     count_deg_scalar_kernel<<<cdiv(e, B), B>>>(dst, e);
    scanA_kernel<<<cdiv(n, CHUNK), 256>>>(n);
    scanB_kernel<<<1, 32>>>(cdiv(n, CHUNK));
    scanC_kernel<<<cdiv(n, B), B>>>(n);
    if (vec) scatter_kernel<<<cdiv(cdiv(e, 4), B), B>>>(src, dst, e);
    else     scatter_scalar_kernel<<<cdiv(e, B), B>>>(src, dst, e);

    // layer 1 GEMM (prescaled)
    gemm1_kernel<<<cdiv(n, GN), 128>>>(x, W1, n);

    // fused layers
    pull4_kernel<4><<<cdiv(n, 256), 256>>>(tmpA, b1, W2, tmpB, n);
    pull4_kernel<2><<<cdiv(n, 256), 256>>>(tmpB, b2, W3, tmpA, n);

    float* out  = (float*)d_out;
    float* hsec = out + (size_t)n * 16;
    pull2_cls_kernel<<<cdiv(n, 256), 256>>>(tmpA, b3, Wc, bc, out, hsec, n);
}